// round 1
// baseline (speedup 1.0000x reference)
#include <cuda_runtime.h>

#define N_ATOMS 50000
#define N_EDGES 640000
#define RBF 64
#define HID 128

// ---------------- scratch (device globals: no runtime allocation) -------------
__device__ __align__(16) float g_P[N_ATOMS * RBF];   // segment-sum of pair_feat
__device__ float g_counts[N_ATOMS];                  // edges per atom (as float)
__device__ __align__(16) float g_Wc[RBF * HID];      // w_rbf @ w_pair
__device__ __align__(16) float g_bc[HID];            // b_rbf @ w_pair + b_pair

// ---------------- kernel 1: zero scratch -------------------------------------
__global__ void zero_kernel() {
    int stride = gridDim.x * blockDim.x;
    int i = blockIdx.x * blockDim.x + threadIdx.x;
    for (int idx = i; idx < N_ATOMS * RBF; idx += stride) g_P[idx] = 0.0f;
    for (int idx = i; idx < N_ATOMS; idx += stride) g_counts[idx] = 0.0f;
}

// ---------------- kernel 2: combined edge weights ----------------------------
// W_c[k][j] = sum_m w_rbf[k][m] * w_pair[m][j];  b_c[j] = sum_m b_rbf[m]*w_pair[m][j] + b_pair[j]
__global__ void wc_kernel(const float* __restrict__ w_rbf,
                          const float* __restrict__ b_rbf,
                          const float* __restrict__ w_pair,
                          const float* __restrict__ b_pair) {
    int idx = blockIdx.x * blockDim.x + threadIdx.x;
    if (idx < RBF * HID) {
        int k = idx / HID, j = idx % HID;
        float s = 0.0f;
        #pragma unroll 8
        for (int m = 0; m < HID; m++) s += w_rbf[k * HID + m] * w_pair[m * HID + j];
        g_Wc[idx] = s;
    }
    if (idx < HID) {
        float s = b_pair[idx];
        #pragma unroll 8
        for (int m = 0; m < HID; m++) s += b_rbf[m] * w_pair[m * HID + idx];
        g_bc[idx] = s;
    }
}

// ---------------- kernel 3: edge scatter (segment-sum of raw pair features) ---
// 16 threads per edge, each handles one float4 chunk of the 64-wide row.
__global__ void __launch_bounds__(256) scatter_kernel(const float4* __restrict__ pair4,
                                                      const int* __restrict__ recv) {
    int gid = blockIdx.x * blockDim.x + threadIdx.x;   // max 10.24M, fits int
    int e = gid >> 4;
    int c = gid & 15;
    if (e >= N_EDGES) return;
    int a = __ldg(&recv[e]);
    float4 v = __ldg(&pair4[e * 16 + c]);
    float* dst = g_P + a * RBF + c * 4;
    asm volatile("red.global.add.v4.f32 [%0], {%1,%2,%3,%4};"
                 :: "l"(dst), "f"(v.x), "f"(v.y), "f"(v.z), "f"(v.w) : "memory");
    if (c == 0) atomicAdd(&g_counts[a], 1.0f);
}

// ---------------- kernel 4: atom-side fused MLP chain ------------------------
// agg = P @ W_c + counts*b_c ; h = silu(agg@w1+b1) ; out = atom + h@w2 + b2
// One warp processes 4 atoms at a time so each smem weight float4 feeds 16 FFMAs
// (keeps us FMA-bound instead of smem-crossbar-bound).
#define AK_THREADS 256
#define AK_WARPS 8
#define AT 4

// smem layout (floats): Wc 8192 | w1 16384 | w2 16384 | b1 128 | b2 128 | bc 128 | warp bufs 8*1280
#define SM_WC   0
#define SM_W1   (SM_WC + RBF * HID)
#define SM_W2   (SM_W1 + HID * HID)
#define SM_B1   (SM_W2 + HID * HID)
#define SM_B2   (SM_B1 + HID)
#define SM_BC   (SM_B2 + HID)
#define SM_BUF  (SM_BC + HID)
#define SM_PER_WARP (AT * RBF + AT * HID + AT * HID)   // 256 + 512 + 512 = 1280
#define SM_FLOATS (SM_BUF + AK_WARPS * SM_PER_WARP)
#define SM_BYTES (SM_FLOATS * 4)

__global__ void __launch_bounds__(AK_THREADS, 1) atom_kernel(
    const float* __restrict__ atom_feat,
    const float* __restrict__ w1, const float* __restrict__ b1,
    const float* __restrict__ w2, const float* __restrict__ b2,
    float* __restrict__ out) {
    extern __shared__ float sm[];

    // cooperative weight staging
    for (int i = threadIdx.x; i < RBF * HID; i += AK_THREADS) sm[SM_WC + i] = g_Wc[i];
    for (int i = threadIdx.x; i < HID * HID; i += AK_THREADS) {
        sm[SM_W1 + i] = w1[i];
        sm[SM_W2 + i] = w2[i];
    }
    for (int i = threadIdx.x; i < HID; i += AK_THREADS) {
        sm[SM_B1 + i] = b1[i];
        sm[SM_B2 + i] = b2[i];
        sm[SM_BC + i] = g_bc[i];
    }
    __syncthreads();

    int warp = threadIdx.x >> 5;
    int lane = threadIdx.x & 31;
    float* pbuf   = sm + SM_BUF + warp * SM_PER_WARP;          // AT*64
    float* aggbuf = pbuf + AT * RBF;                           // AT*128
    float* hbuf   = aggbuf + AT * HID;                         // AT*128

    int gw = blockIdx.x * AK_WARPS + warp;
    int nw = gridDim.x * AK_WARPS;
    int j0 = lane * 4;

    float4 bc4 = ((const float4*)(sm + SM_BC))[lane];
    float4 b14 = ((const float4*)(sm + SM_B1))[lane];
    float4 b24 = ((const float4*)(sm + SM_B2))[lane];

    for (int g = gw; g * AT < N_ATOMS; g += nw) {
        int a0 = g * AT;

        // stage P rows for 4 atoms: 64 float4 chunks, 2 per lane
        #pragma unroll
        for (int t = 0; t < 2; t++) {
            int idx = lane + 32 * t;        // 0..63
            int at = idx >> 4, ch = idx & 15;
            ((float4*)pbuf)[at * 16 + ch] =
                *(const float4*)(g_P + (a0 + at) * RBF + ch * 4);
        }
        __syncwarp();

        // ---- GEMM1: agg = P@Wc + cnt*bc  (64 -> 128) ----
        float4 acc[AT];
        #pragma unroll
        for (int t = 0; t < AT; t++) {
            float cnt = g_counts[a0 + t];
            acc[t].x = cnt * bc4.x; acc[t].y = cnt * bc4.y;
            acc[t].z = cnt * bc4.z; acc[t].w = cnt * bc4.w;
        }
        #pragma unroll 8
        for (int k = 0; k < RBF; k++) {
            float4 w = ((const float4*)(sm + SM_WC + k * HID))[lane];
            #pragma unroll
            for (int t = 0; t < AT; t++) {
                float pk = pbuf[t * RBF + k];
                acc[t].x += pk * w.x; acc[t].y += pk * w.y;
                acc[t].z += pk * w.z; acc[t].w += pk * w.w;
            }
        }
        #pragma unroll
        for (int t = 0; t < AT; t++) ((float4*)(aggbuf + t * HID))[lane] = acc[t];
        __syncwarp();

        // ---- GEMM2 + silu: h = silu(agg@w1 + b1) ----
        float4 h[AT];
        #pragma unroll
        for (int t = 0; t < AT; t++) h[t] = b14;
        #pragma unroll 4
        for (int k = 0; k < HID; k++) {
            float4 w = ((const float4*)(sm + SM_W1 + k * HID))[lane];
            #pragma unroll
            for (int t = 0; t < AT; t++) {
                float xk = aggbuf[t * HID + k];
                h[t].x += xk * w.x; h[t].y += xk * w.y;
                h[t].z += xk * w.z; h[t].w += xk * w.w;
            }
        }
        #pragma unroll
        for (int t = 0; t < AT; t++) {
            h[t].x = h[t].x / (1.0f + __expf(-h[t].x));
            h[t].y = h[t].y / (1.0f + __expf(-h[t].y));
            h[t].z = h[t].z / (1.0f + __expf(-h[t].z));
            h[t].w = h[t].w / (1.0f + __expf(-h[t].w));
            ((float4*)(hbuf + t * HID))[lane] = h[t];
        }
        __syncwarp();

        // ---- GEMM3 + residual: out = atom + h@w2 + b2 ----
        float4 o[AT];
        #pragma unroll
        for (int t = 0; t < AT; t++) o[t] = b24;
        #pragma unroll 4
        for (int k = 0; k < HID; k++) {
            float4 w = ((const float4*)(sm + SM_W2 + k * HID))[lane];
            #pragma unroll
            for (int t = 0; t < AT; t++) {
                float hk = hbuf[t * HID + k];
                o[t].x += hk * w.x; o[t].y += hk * w.y;
                o[t].z += hk * w.z; o[t].w += hk * w.w;
            }
        }
        #pragma unroll
        for (int t = 0; t < AT; t++) {
            float4 af = *(const float4*)(atom_feat + (a0 + t) * HID + j0);
            o[t].x += af.x; o[t].y += af.y; o[t].z += af.z; o[t].w += af.w;
            *(float4*)(out + (a0 + t) * HID + j0) = o[t];
        }
        __syncwarp();   // protect warp buffers before next iteration
    }
}

// ---------------- launch ------------------------------------------------------
extern "C" void kernel_launch(void* const* d_in, const int* in_sizes, int n_in,
                              void* d_out, int out_size) {
    (void)in_sizes; (void)n_in; (void)out_size;
    const float* atom_feat = (const float*)d_in[0];
    const float* pair_feat = (const float*)d_in[1];
    const int*   recv_idx  = (const int*)d_in[2];
    const float* w_rbf     = (const float*)d_in[3];
    const float* b_rbf     = (const float*)d_in[4];
    const float* w_pair    = (const float*)d_in[5];
    const float* b_pair    = (const float*)d_in[6];
    const float* w1        = (const float*)d_in[7];
    const float* b1        = (const float*)d_in[8];
    const float* w2        = (const float*)d_in[9];
    const float* b2        = (const float*)d_in[10];
    float* out = (float*)d_out;

    cudaFuncSetAttribute(atom_kernel, cudaFuncAttributeMaxDynamicSharedMemorySize, SM_BYTES);

    zero_kernel<<<256, 256>>>();
    wc_kernel<<<(RBF * HID + 255) / 256, 256>>>(w_rbf, b_rbf, w_pair, b_pair);
    scatter_kernel<<<(N_EDGES * 16) / 256, 256>>>((const float4*)pair_feat, recv_idx);
    atom_kernel<<<148, AK_THREADS, SM_BYTES>>>(atom_feat, w1, b1, w2, b2, out);
}

// round 3
// speedup vs baseline: 1.6153x; 1.6153x over previous
#include <cuda_runtime.h>
#include <cstdint>

#define N_ATOMS 50000
#define N_PAD   50048
#define N_EDGES 640000
#define RBF 64
#define HID 128
#define NTILES 391              // ceil(50000/128)

// ---------------- device scratch (no runtime allocation) ---------------------
__device__ __align__(16) float g_P[N_PAD * RBF];      // segment-sum of pair_feat (tf32-rounded at stage time)
__device__ __align__(16) float g_counts[N_PAD];       // edges per atom
__device__ __align__(16) float g_Wc[RBF * HID];       // (w_rbf@w_pair), tf32-rounded, [k][n]
__device__ __align__(16) float g_bc[HID];             // b_rbf@w_pair + b_pair (fp32)

// ---------------- helpers -----------------------------------------------------
__device__ __forceinline__ float to_tf32(float x) {
    uint32_t r;
    asm("cvt.rna.tf32.f32 %0, %1;" : "=r"(r) : "f"(x));
    return __uint_as_float(r);
}

__device__ __forceinline__ void mma8(float* d, const uint32_t* a, uint32_t b0, uint32_t b1) {
    asm("mma.sync.aligned.m16n8k8.row.col.f32.tf32.tf32.f32 "
        "{%0,%1,%2,%3}, {%4,%5,%6,%7}, {%8,%9}, {%0,%1,%2,%3};"
        : "+f"(d[0]), "+f"(d[1]), "+f"(d[2]), "+f"(d[3])
        : "r"(a[0]), "r"(a[1]), "r"(a[2]), "r"(a[3]), "r"(b0), "r"(b1));
}

// ---------------- kernel 1: zero scratch -------------------------------------
__global__ void zero_kernel() {
    int stride = gridDim.x * blockDim.x;
    int i = blockIdx.x * blockDim.x + threadIdx.x;
    for (int idx = i; idx < N_PAD * RBF; idx += stride) g_P[idx] = 0.0f;
    for (int idx = i; idx < N_PAD; idx += stride) g_counts[idx] = 0.0f;
}

// ---------------- kernel 2: fold edge weights, round to tf32 ------------------
__global__ void prep_kernel(const float* __restrict__ w_rbf, const float* __restrict__ b_rbf,
                            const float* __restrict__ w_pair, const float* __restrict__ b_pair) {
    int idx = blockIdx.x * blockDim.x + threadIdx.x;
    if (idx < RBF * HID) {               // Wc[k][n] = sum_m w_rbf[k][m] * w_pair[m][n]
        int k = idx >> 7, n = idx & 127;
        float s = 0.0f;
        #pragma unroll 8
        for (int m = 0; m < HID; m++) s += w_rbf[k * HID + m] * w_pair[m * HID + n];
        g_Wc[idx] = to_tf32(s);
    }
    if (idx < HID) {                     // bc[n] = b_pair[n] + sum_m b_rbf[m]*w_pair[m][n]
        float s = b_pair[idx];
        #pragma unroll 8
        for (int m = 0; m < HID; m++) s += b_rbf[m] * w_pair[m * HID + idx];
        g_bc[idx] = s;
    }
}

// ---------------- kernel 3: edge scatter --------------------------------------
__global__ void __launch_bounds__(256) scatter_kernel(const float4* __restrict__ pair4,
                                                      const int* __restrict__ recv) {
    int gid = blockIdx.x * blockDim.x + threadIdx.x;
    int e = gid >> 4;
    int c = gid & 15;
    if (e >= N_EDGES) return;
    int a = __ldg(&recv[e]);
    float4 v = __ldg(&pair4[e * 16 + c]);
    float* dst = g_P + a * RBF + c * 4;
    asm volatile("red.global.add.v4.f32 [%0], {%1,%2,%3,%4};"
                 :: "l"(dst), "f"(v.x), "f"(v.y), "f"(v.z), "f"(v.w) : "memory");
    if (c == 0) atomicAdd(&g_counts[a], 1.0f);
}

// ---------------- kernel 4: persistent tf32-mma atom MLP chain ----------------
// One tile = 128 atoms. Warp grid 4(m) x 2(n); warp tile 32x64 of the 128x128 output.
// Smem (floats):
#define SX  0                       // X buffer 128x128 (row stride 128, XOR swizzle)
#define SWC 16384                   // Wc 64x128
#define SW1 24576                   // W1 128x128
#define SW2 40960                   // W2 128x128
#define SBC 57344
#define SB1 57472
#define SB2 57600
#define SM_FLOATS 57728
#define SMEM_BYTES (SM_FLOATS * 4)  // 230912 B <= 232448 max

// swizzles (16B-granular: float4 stores stay contiguous)
#define SWZ_A(m, k) ((m) * 128 + ((k) ^ (((m) & 7) << 2)))
#define SWZ_B(k, n) ((k) * 128 + ((n) ^ (((k) & 3) << 3)))

template <int KSTEPS>
__device__ __forceinline__ void gemm_tile(const float* __restrict__ sA,
                                          const float* __restrict__ sB,
                                          int m0, int n0, int lr, int lc,
                                          float acc[2][8][4]) {
    #pragma unroll 4
    for (int ks = 0; ks < KSTEPS; ks++) {
        int k0 = ks * 8;
        uint32_t a[2][4];
        #pragma unroll
        for (int f = 0; f < 2; f++) {
            int mb = m0 + f * 16;
            // (mb+lr)&7 == lr and (mb+lr+8)&7 == lr  (mb multiple of 16)
            a[f][0] = __float_as_uint(sA[(mb + lr) * 128     + ((k0 + lc)     ^ (lr << 2))]);
            a[f][1] = __float_as_uint(sA[(mb + lr + 8) * 128 + ((k0 + lc)     ^ (lr << 2))]);
            a[f][2] = __float_as_uint(sA[(mb + lr) * 128     + ((k0 + lc + 4) ^ (lr << 2))]);
            a[f][3] = __float_as_uint(sA[(mb + lr + 8) * 128 + ((k0 + lc + 4) ^ (lr << 2))]);
        }
        #pragma unroll
        for (int g = 0; g < 8; g++) {
            int nb = n0 + g * 8 + lr;
            // (k0+lc)&3 == lc == (k0+lc+4)&3
            uint32_t b0 = __float_as_uint(sB[(k0 + lc) * 128     + (nb ^ (lc << 3))]);
            uint32_t b1 = __float_as_uint(sB[(k0 + lc + 4) * 128 + (nb ^ (lc << 3))]);
            mma8(acc[0][g], a[0], b0, b1);
            mma8(acc[1][g], a[1], b0, b1);
        }
    }
}

__global__ void __launch_bounds__(256, 1) atom_mma_kernel(
    const float* __restrict__ atom_feat,
    const float* __restrict__ w1g, const float* __restrict__ b1g,
    const float* __restrict__ w2g, const float* __restrict__ b2g,
    float* __restrict__ out) {
    extern __shared__ float sm[];
    int tid = threadIdx.x;

    // ---- one-time staging: weights (swizzled) + biases ----
    for (int i4 = tid; i4 < 2048; i4 += 256) {          // Wc 64x128 (already tf32)
        int k = i4 >> 5, n4 = (i4 & 31) << 2;
        float4 v = *(const float4*)(g_Wc + k * 128 + n4);
        *(float4*)&sm[SWC + SWZ_B(k, n4)] = v;
    }
    for (int i4 = tid; i4 < 4096; i4 += 256) {          // W1, W2 128x128 (round here)
        int k = i4 >> 5, n4 = (i4 & 31) << 2;
        float4 v1 = *(const float4*)(w1g + k * 128 + n4);
        float4 v2 = *(const float4*)(w2g + k * 128 + n4);
        v1.x = to_tf32(v1.x); v1.y = to_tf32(v1.y); v1.z = to_tf32(v1.z); v1.w = to_tf32(v1.w);
        v2.x = to_tf32(v2.x); v2.y = to_tf32(v2.y); v2.z = to_tf32(v2.z); v2.w = to_tf32(v2.w);
        int o = SWZ_B(k, n4);
        *(float4*)&sm[SW1 + o] = v1;
        *(float4*)&sm[SW2 + o] = v2;
    }
    if (tid < HID) {
        sm[SBC + tid] = g_bc[tid];
        sm[SB1 + tid] = b1g[tid];
        sm[SB2 + tid] = b2g[tid];
    }

    int warp = tid >> 5;
    int lane = tid & 31;
    int lr = lane >> 2;            // 0..7
    int lc = lane & 3;             // 0..3
    int m0 = (warp & 3) * 32;
    int n0 = (warp >> 2) * 64;

    float acc[2][8][4];

    for (int tile = blockIdx.x; tile < NTILES; tile += gridDim.x) {
        int tbase = tile * 128;

        __syncthreads();   // previous tile's GEMM3 reads finished before overwriting sX
        // ---- stage X = g_P tile (128 x 64), tf32-rounded, swizzled ----
        for (int i4 = tid; i4 < 2048; i4 += 256) {
            int m = i4 >> 4, k4 = (i4 & 15) << 2;
            float4 v = *(const float4*)(g_P + (tbase + m) * RBF + k4);
            v.x = to_tf32(v.x); v.y = to_tf32(v.y); v.z = to_tf32(v.z); v.w = to_tf32(v.w);
            *(float4*)&sm[SX + SWZ_A(m, k4)] = v;
        }
        __syncthreads();

        // ---- GEMM1: agg = P @ Wc (K=64) ----
        #pragma unroll
        for (int f = 0; f < 2; f++)
            #pragma unroll
            for (int g = 0; g < 8; g++)
                #pragma unroll
                for (int q = 0; q < 4; q++) acc[f][g][q] = 0.0f;
        gemm_tile<8>(sm + SX, sm + SWC, m0, n0, lr, lc, acc);
        __syncthreads();   // all warps done reading P region

        // ---- epi1: X = tf32(agg + cnt*bc) ----
        #pragma unroll
        for (int f = 0; f < 2; f++) {
            int lm0 = m0 + f * 16 + lr;
            float cnt0 = g_counts[tbase + lm0];
            float cnt1 = g_counts[tbase + lm0 + 8];
            #pragma unroll
            for (int g = 0; g < 8; g++) {
                int c0 = n0 + g * 8 + 2 * lc;
                float bc0 = sm[SBC + c0], bc1 = sm[SBC + c0 + 1];
                float2 v0, v1;
                v0.x = to_tf32(acc[f][g][0] + cnt0 * bc0);
                v0.y = to_tf32(acc[f][g][1] + cnt0 * bc1);
                v1.x = to_tf32(acc[f][g][2] + cnt1 * bc0);
                v1.y = to_tf32(acc[f][g][3] + cnt1 * bc1);
                int co = c0 ^ (lr << 2);
                *(float2*)&sm[SX + lm0 * 128 + co] = v0;
                *(float2*)&sm[SX + (lm0 + 8) * 128 + co] = v1;
            }
        }
        __syncthreads();

        // ---- GEMM2: pre = agg @ W1 (K=128) ----
        #pragma unroll
        for (int f = 0; f < 2; f++)
            #pragma unroll
            for (int g = 0; g < 8; g++)
                #pragma unroll
                for (int q = 0; q < 4; q++) acc[f][g][q] = 0.0f;
        gemm_tile<16>(sm + SX, sm + SW1, m0, n0, lr, lc, acc);
        __syncthreads();

        // ---- epi2: X = tf32(silu(pre + b1)) ----
        #pragma unroll
        for (int f = 0; f < 2; f++) {
            int lm0 = m0 + f * 16 + lr;
            #pragma unroll
            for (int g = 0; g < 8; g++) {
                int c0 = n0 + g * 8 + 2 * lc;
                float b10 = sm[SB1 + c0], b11 = sm[SB1 + c0 + 1];
                float x00 = acc[f][g][0] + b10;
                float x01 = acc[f][g][1] + b11;
                float x10 = acc[f][g][2] + b10;
                float x11 = acc[f][g][3] + b11;
                float2 v0, v1;
                v0.x = to_tf32(x00 / (1.0f + __expf(-x00)));
                v0.y = to_tf32(x01 / (1.0f + __expf(-x01)));
                v1.x = to_tf32(x10 / (1.0f + __expf(-x10)));
                v1.y = to_tf32(x11 / (1.0f + __expf(-x11)));
                int co = c0 ^ (lr << 2);
                *(float2*)&sm[SX + lm0 * 128 + co] = v0;
                *(float2*)&sm[SX + (lm0 + 8) * 128 + co] = v1;
            }
        }
        __syncthreads();

        // ---- GEMM3: corr = h @ W2 (K=128) ----
        #pragma unroll
        for (int f = 0; f < 2; f++)
            #pragma unroll
            for (int g = 0; g < 8; g++)
                #pragma unroll
                for (int q = 0; q < 4; q++) acc[f][g][q] = 0.0f;
        gemm_tile<16>(sm + SX, sm + SW2, m0, n0, lr, lc, acc);

        // ---- epi3: out = atom_feat + corr + b2 (global) ----
        #pragma unroll
        for (int f = 0; f < 2; f++) {
            int lm0 = m0 + f * 16 + lr;
            int ar0 = tbase + lm0;
            int ar1 = ar0 + 8;
            #pragma unroll
            for (int g = 0; g < 8; g++) {
                int c0 = n0 + g * 8 + 2 * lc;
                float b20 = sm[SB2 + c0], b21 = sm[SB2 + c0 + 1];
                if (ar0 < N_ATOMS) {
                    float2 af = *(const float2*)(atom_feat + ar0 * HID + c0);
                    float2 o;
                    o.x = acc[f][g][0] + b20 + af.x;
                    o.y = acc[f][g][1] + b21 + af.y;
                    *(float2*)(out + ar0 * HID + c0) = o;
                }
                if (ar1 < N_ATOMS) {
                    float2 af = *(const float2*)(atom_feat + ar1 * HID + c0);
                    float2 o;
                    o.x = acc[f][g][2] + b20 + af.x;
                    o.y = acc[f][g][3] + b21 + af.y;
                    *(float2*)(out + ar1 * HID + c0) = o;
                }
            }
        }
        // top-of-loop __syncthreads() protects sX before next staging
    }
}

// ---------------- launch ------------------------------------------------------
extern "C" void kernel_launch(void* const* d_in, const int* in_sizes, int n_in,
                              void* d_out, int out_size) {
    (void)in_sizes; (void)n_in; (void)out_size;
    const float* atom_feat = (const float*)d_in[0];
    const float* pair_feat = (const float*)d_in[1];
    const int*   recv_idx  = (const int*)d_in[2];
    const float* w_rbf     = (const float*)d_in[3];
    const float* b_rbf     = (const float*)d_in[4];
    const float* w_pair    = (const float*)d_in[5];
    const float* b_pair    = (const float*)d_in[6];
    const float* w1        = (const float*)d_in[7];
    const float* b1        = (const float*)d_in[8];
    const float* w2        = (const float*)d_in[9];
    const float* b2        = (const float*)d_in[10];
    float* out = (float*)d_out;

    cudaFuncSetAttribute(atom_mma_kernel, cudaFuncAttributeMaxDynamicSharedMemorySize, SMEM_BYTES);

    zero_kernel<<<256, 256>>>();
    prep_kernel<<<32, 256>>>(w_rbf, b_rbf, w_pair, b_pair);
    scatter_kernel<<<(N_EDGES * 16) / 256, 256>>>((const float4*)pair_feat, recv_idx);
    atom_mma_kernel<<<148, 256, SMEM_BYTES>>>(atom_feat, w1, b1, w2, b2, out);
}

// round 4
// speedup vs baseline: 1.7411x; 1.0778x over previous
#include <cuda_runtime.h>
#include <cstdint>

#define N_ATOMS 50000
#define N_PAD   50048
#define N_EDGES 640000
#define RBF 64
#define HID 128
#define NMICRO 3125             // 50000 / 16 micro-tiles of 16 atoms

// ---------------- device scratch (no runtime allocation) ---------------------
__device__ __align__(16) float g_P[N_PAD * RBF];      // segment-sum of pair_feat
__device__ __align__(16) float g_counts[N_PAD];       // edges per atom
__device__ __align__(16) float g_Wc[RBF * HID];       // (w_rbf@w_pair), tf32-rounded, [k][n]
__device__ __align__(16) float g_bc[HID];             // b_rbf@w_pair + b_pair (fp32)

// ---------------- helpers -----------------------------------------------------
__device__ __forceinline__ float to_tf32(float x) {
    uint32_t r;
    asm("cvt.rna.tf32.f32 %0, %1;" : "=r"(r) : "f"(x));
    return __uint_as_float(r);
}

__device__ __forceinline__ void mma8(float* d, const uint32_t* a, uint32_t b0, uint32_t b1) {
    asm("mma.sync.aligned.m16n8k8.row.col.f32.tf32.tf32.f32 "
        "{%0,%1,%2,%3}, {%4,%5,%6,%7}, {%8,%9}, {%0,%1,%2,%3};"
        : "+f"(d[0]), "+f"(d[1]), "+f"(d[2]), "+f"(d[3])
        : "r"(a[0]), "r"(a[1]), "r"(a[2]), "r"(a[3]), "r"(b0), "r"(b1));
}

// ---------------- kernel 1: zero scratch -------------------------------------
__global__ void zero_kernel() {
    int stride = gridDim.x * blockDim.x;
    int i = blockIdx.x * blockDim.x + threadIdx.x;
    for (int idx = i; idx < N_PAD * RBF; idx += stride) g_P[idx] = 0.0f;
    for (int idx = i; idx < N_PAD; idx += stride) g_counts[idx] = 0.0f;
}

// ---------------- kernel 2: fold edge weights, round to tf32 ------------------
__global__ void prep_kernel(const float* __restrict__ w_rbf, const float* __restrict__ b_rbf,
                            const float* __restrict__ w_pair, const float* __restrict__ b_pair) {
    int idx = blockIdx.x * blockDim.x + threadIdx.x;
    if (idx < RBF * HID) {               // Wc[k][n] = sum_m w_rbf[k][m] * w_pair[m][n]
        int k = idx >> 7, n = idx & 127;
        float s = 0.0f;
        #pragma unroll 8
        for (int m = 0; m < HID; m++) s += w_rbf[k * HID + m] * w_pair[m * HID + n];
        g_Wc[idx] = to_tf32(s);
    }
    if (idx < HID) {                     // bc[n] = b_pair[n] + sum_m b_rbf[m]*w_pair[m][n]
        float s = b_pair[idx];
        #pragma unroll 8
        for (int m = 0; m < HID; m++) s += b_rbf[m] * w_pair[m * HID + idx];
        g_bc[idx] = s;
    }
}

// ---------------- kernel 3: edge scatter --------------------------------------
__global__ void __launch_bounds__(256) scatter_kernel(const float4* __restrict__ pair4,
                                                      const int* __restrict__ recv) {
    int gid = blockIdx.x * blockDim.x + threadIdx.x;
    int e = gid >> 4;
    int c = gid & 15;
    if (e >= N_EDGES) return;
    int a = __ldg(&recv[e]);
    float4 v = __ldg(&pair4[e * 16 + c]);
    float* dst = g_P + a * RBF + c * 4;
    asm volatile("red.global.add.v4.f32 [%0], {%1,%2,%3,%4};"
                 :: "l"(dst), "f"(v.x), "f"(v.y), "f"(v.z), "f"(v.w) : "memory");
    if (c == 0) atomicAdd(&g_counts[a], 1.0f);
}

// ---------------- kernel 4: persistent tf32-mma atom MLP chain ----------------
// Warp-decoupled: each warp owns a 16-atom micro-tile (m=16, n=128) and its own
// 16x128 X slice in smem. No block barriers in the tile loop.
#define SX  0                       // X: 8 warps x 16 rows x 128 cols
#define SWC 16384                   // Wc 64x128 (swizzled)
#define SW1 24576                   // W1 128x128
#define SW2 40960                   // W2 128x128
#define SBC 57344
#define SB1 57472
#define SB2 57600
#define SM_FLOATS 57728
#define SMEM_BYTES (SM_FLOATS * 4)  // 230912 B

#define SWZ_A(m, k) ((m) * 128 + ((k) ^ (((m) & 7) << 2)))
#define SWZ_B(k, n) ((k) * 128 + ((n) ^ (((k) & 3) << 3)))

// one K-slab of the warp GEMM: A frag (m=16) vs 16 n-blocks
template <int KSTEPS>
__device__ __forceinline__ void gemm_warp(const float* __restrict__ sA,
                                          const float* __restrict__ sB,
                                          int lr, int lc, float acc[16][4]) {
    #pragma unroll 4
    for (int ks = 0; ks < KSTEPS; ks++) {
        int k0 = ks * 8;
        uint32_t a[4];
        a[0] = __float_as_uint(sA[lr * 128       + ((k0 + lc)     ^ (lr << 2))]);
        a[1] = __float_as_uint(sA[(lr + 8) * 128 + ((k0 + lc)     ^ (lr << 2))]);
        a[2] = __float_as_uint(sA[lr * 128       + ((k0 + lc + 4) ^ (lr << 2))]);
        a[3] = __float_as_uint(sA[(lr + 8) * 128 + ((k0 + lc + 4) ^ (lr << 2))]);
        #pragma unroll
        for (int g = 0; g < 16; g++) {
            int nb = g * 8 + lr;
            uint32_t b0 = __float_as_uint(sB[(k0 + lc) * 128     + (nb ^ (lc << 3))]);
            uint32_t b1 = __float_as_uint(sB[(k0 + lc + 4) * 128 + (nb ^ (lc << 3))]);
            mma8(acc[g], a, b0, b1);
        }
    }
}

__global__ void __launch_bounds__(256, 1) atom_mma_kernel(
    const float* __restrict__ atom_feat,
    const float* __restrict__ w1g, const float* __restrict__ b1g,
    const float* __restrict__ w2g, const float* __restrict__ b2g,
    float* __restrict__ out) {
    extern __shared__ float sm[];
    int tid = threadIdx.x;

    // ---- one-time staging: weights (swizzled) + biases ----
    for (int i4 = tid; i4 < 2048; i4 += 256) {          // Wc 64x128 (already tf32)
        int k = i4 >> 5, n4 = (i4 & 31) << 2;
        float4 v = *(const float4*)(g_Wc + k * 128 + n4);
        *(float4*)&sm[SWC + SWZ_B(k, n4)] = v;
    }
    for (int i4 = tid; i4 < 4096; i4 += 256) {          // W1, W2 128x128 (round here)
        int k = i4 >> 5, n4 = (i4 & 31) << 2;
        float4 v1 = *(const float4*)(w1g + k * 128 + n4);
        float4 v2 = *(const float4*)(w2g + k * 128 + n4);
        v1.x = to_tf32(v1.x); v1.y = to_tf32(v1.y); v1.z = to_tf32(v1.z); v1.w = to_tf32(v1.w);
        v2.x = to_tf32(v2.x); v2.y = to_tf32(v2.y); v2.z = to_tf32(v2.z); v2.w = to_tf32(v2.w);
        int o = SWZ_B(k, n4);
        *(float4*)&sm[SW1 + o] = v1;
        *(float4*)&sm[SW2 + o] = v2;
    }
    if (tid < HID) {
        sm[SBC + tid] = g_bc[tid];
        sm[SB1 + tid] = b1g[tid];
        sm[SB2 + tid] = b2g[tid];
    }
    __syncthreads();            // only block barrier in the kernel

    int warp = tid >> 5;
    int lane = tid & 31;
    int lr = lane >> 2;         // 0..7
    int lc = lane & 3;          // 0..3

    float* sX = sm + SX + warp * (16 * 128);    // warp-private 16x128 slice
    const float* sWc = sm + SWC;
    const float* sW1 = sm + SW1;
    const float* sW2 = sm + SW2;

    float acc[16][4];

    for (int mt = blockIdx.x * 8 + warp; mt < NMICRO; mt += 148 * 8) {
        int rbase = mt * 16;

        // ---- stage P micro-tile (16x64), tf32-rounded, swizzled ----
        #pragma unroll
        for (int i = 0; i < 8; i++) {
            int i4 = lane + 32 * i;             // 0..255
            int m = i4 >> 4;                    // 0..15
            int k4 = (i4 & 15) << 2;            // 0,4,..,60
            float4 v = *(const float4*)(g_P + (rbase + m) * RBF + k4);
            v.x = to_tf32(v.x); v.y = to_tf32(v.y); v.z = to_tf32(v.z); v.w = to_tf32(v.w);
            *(float4*)&sX[SWZ_A(m, k4)] = v;
        }
        __syncwarp();

        // ---- GEMM1: agg = P @ Wc (K=64) ----
        #pragma unroll
        for (int g = 0; g < 16; g++)
            #pragma unroll
            for (int q = 0; q < 4; q++) acc[g][q] = 0.0f;
        gemm_warp<8>(sX, sWc, lr, lc, acc);
        __syncwarp();

        // ---- epi1: X = tf32(agg + cnt*bc) ----
        {
            float cnt0 = g_counts[rbase + lr];
            float cnt1 = g_counts[rbase + lr + 8];
            #pragma unroll
            for (int g = 0; g < 16; g++) {
                int c0 = g * 8 + 2 * lc;
                float2 bc = *(const float2*)&sm[SBC + c0];
                float2 v0, v1;
                v0.x = to_tf32(acc[g][0] + cnt0 * bc.x);
                v0.y = to_tf32(acc[g][1] + cnt0 * bc.y);
                v1.x = to_tf32(acc[g][2] + cnt1 * bc.x);
                v1.y = to_tf32(acc[g][3] + cnt1 * bc.y);
                int co = c0 ^ (lr << 2);
                *(float2*)&sX[lr * 128 + co] = v0;
                *(float2*)&sX[(lr + 8) * 128 + co] = v1;
            }
        }
        __syncwarp();

        // ---- GEMM2: pre = agg @ W1 (K=128) ----
        #pragma unroll
        for (int g = 0; g < 16; g++)
            #pragma unroll
            for (int q = 0; q < 4; q++) acc[g][q] = 0.0f;
        gemm_warp<16>(sX, sW1, lr, lc, acc);
        __syncwarp();

        // ---- epi2: X = tf32(silu(pre + b1)) ----
        #pragma unroll
        for (int g = 0; g < 16; g++) {
            int c0 = g * 8 + 2 * lc;
            float2 b1v = *(const float2*)&sm[SB1 + c0];
            float x00 = acc[g][0] + b1v.x;
            float x01 = acc[g][1] + b1v.y;
            float x10 = acc[g][2] + b1v.x;
            float x11 = acc[g][3] + b1v.y;
            float2 v0, v1;
            v0.x = to_tf32(x00 / (1.0f + __expf(-x00)));
            v0.y = to_tf32(x01 / (1.0f + __expf(-x01)));
            v1.x = to_tf32(x10 / (1.0f + __expf(-x10)));
            v1.y = to_tf32(x11 / (1.0f + __expf(-x11)));
            int co = c0 ^ (lr << 2);
            *(float2*)&sX[lr * 128 + co] = v0;
            *(float2*)&sX[(lr + 8) * 128 + co] = v1;
        }
        __syncwarp();

        // ---- GEMM3: corr = h @ W2 (K=128) ----
        #pragma unroll
        for (int g = 0; g < 16; g++)
            #pragma unroll
            for (int q = 0; q < 4; q++) acc[g][q] = 0.0f;
        gemm_warp<16>(sX, sW2, lr, lc, acc);

        // ---- epi3: out = atom_feat + corr + b2 (rows always < 50000) ----
        {
            int ar0 = rbase + lr;
            int ar1 = ar0 + 8;
            #pragma unroll
            for (int g = 0; g < 16; g++) {
                int c0 = g * 8 + 2 * lc;
                float2 b2v = *(const float2*)&sm[SB2 + c0];
                float2 af0 = *(const float2*)(atom_feat + ar0 * HID + c0);
                float2 af1 = *(const float2*)(atom_feat + ar1 * HID + c0);
                float2 o0, o1;
                o0.x = acc[g][0] + b2v.x + af0.x;
                o0.y = acc[g][1] + b2v.y + af0.y;
                o1.x = acc[g][2] + b2v.x + af1.x;
                o1.y = acc[g][3] + b2v.y + af1.y;
                *(float2*)(out + ar0 * HID + c0) = o0;
                *(float2*)(out + ar1 * HID + c0) = o1;
            }
        }
        __syncwarp();   // X reuse safety before next micro-tile staging
    }
}

// ---------------- launch ------------------------------------------------------
extern "C" void kernel_launch(void* const* d_in, const int* in_sizes, int n_in,
                              void* d_out, int out_size) {
    (void)in_sizes; (void)n_in; (void)out_size;
    const float* atom_feat = (const float*)d_in[0];
    const float* pair_feat = (const float*)d_in[1];
    const int*   recv_idx  = (const int*)d_in[2];
    const float* w_rbf     = (const float*)d_in[3];
    const float* b_rbf     = (const float*)d_in[4];
    const float* w_pair    = (const float*)d_in[5];
    const float* b_pair    = (const float*)d_in[6];
    const float* w1        = (const float*)d_in[7];
    const float* b1        = (const float*)d_in[8];
    const float* w2        = (const float*)d_in[9];
    const float* b2        = (const float*)d_in[10];
    float* out = (float*)d_out;

    cudaFuncSetAttribute(atom_mma_kernel, cudaFuncAttributeMaxDynamicSharedMemorySize, SMEM_BYTES);

    zero_kernel<<<256, 256>>>();
    prep_kernel<<<32, 256>>>(w_rbf, b_rbf, w_pair, b_pair);
    scatter_kernel<<<(N_EDGES * 16) / 256, 256>>>((const float4*)pair_feat, recv_idx);
    atom_mma_kernel<<<148, 256, SMEM_BYTES>>>(atom_feat, w1, b1, w2, b2, out);
}